// round 2
// baseline (speedup 1.0000x reference)
#include <cuda_runtime.h>
#include <cstdint>

// Base-10 ripple-carry addition of digit arrays, parallelized with
// warp-level carry-lookahead (Kogge-Stone scan over generate/propagate).
//
// Layout: one warp per row (64 digits). Lane l owns LSB-order digit
// positions 2l and 2l+1, i.e. columns 63-2l and 62-2l. Those two columns
// are one float2 at float2-index (31 - l) => coalesced 256B/warp/array.
//
// Semantics match the reference exactly for integer digits 0..9:
//   u = a+b+carry_in (<= 19), carry_out = (u >= 10), digit = u - 10*carry_out.

static constexpr int BATCH   = 524288;
static constexpr int SEQ_LEN = 64;

__global__ __launch_bounds__(256)
void adder_kernel(const float* __restrict__ a,
                  const float* __restrict__ b,
                  float* __restrict__ out)
{
    const unsigned tid  = blockIdx.x * blockDim.x + threadIdx.x;
    const unsigned row  = tid >> 5;          // one warp per row
    const unsigned lane = tid & 31u;
    if (row >= (unsigned)BATCH) return;

    const float2* __restrict__ a2 = reinterpret_cast<const float2*>(a);
    const float2* __restrict__ b2 = reinterpret_cast<const float2*>(b);
    float2* __restrict__ o2       = reinterpret_cast<float2*>(out);

    // float2 index within the row: lane 0 -> index 31 (columns 62,63 = LSBs)
    const size_t idx = (size_t)row * 32 + (31 - lane);

    const float2 av = a2[idx];
    const float2 bv = b2[idx];

    // .y = column 63-2l = LSB of this lane's pair (position 2l)
    // .x = column 62-2l = MSB of this lane's pair (position 2l+1)
    const int s_lo = (int)av.y + (int)bv.y;
    const int s_hi = (int)av.x + (int)bv.x;

    // generate/propagate per digit, composed over the 2-digit segment
    const int g_lo = (s_lo >= 10);
    const int p_lo = (s_lo == 9);
    const int g_hi = (s_hi >= 10);
    const int p_hi = (s_hi == 9);

    int G = g_hi | (p_hi & g_lo);   // segment generates a carry
    int P = p_hi & p_lo;            // segment propagates an incoming carry

    // Inclusive Kogge-Stone scan of (G,P) across lanes (lane 0 = lowest seg).
    // Composition lower-then-higher: G = G | (P & G_lower), P = P & P_lower.
    #pragma unroll
    for (int d = 1; d < 32; d <<= 1) {
        const int Gp = __shfl_up_sync(0xFFFFFFFFu, G, d);
        const int Pp = __shfl_up_sync(0xFFFFFFFFu, P, d);
        if ((int)lane >= d) {
            G = G | (P & Gp);
            P = P & Pp;
        }
    }

    // Incoming carry for this lane = scanned G of lane-1 (exclusive scan).
    const int Gprev = __shfl_up_sync(0xFFFFFFFFu, G, 1);
    const int c_in  = (lane == 0) ? 0 : Gprev;

    // Resolve the two digits locally.
    const int t0 = s_lo + c_in;
    const int c0 = (t0 >= 10);
    const int d_lo = t0 - 10 * c0;

    const int t1 = s_hi + c0;
    const int c1 = (t1 >= 10);
    const int d_hi = t1 - 10 * c1;
    (void)c1; // final carry-out is dropped, as in the reference

    o2[idx] = make_float2((float)d_hi, (float)d_lo);
}

extern "C" void kernel_launch(void* const* d_in, const int* in_sizes, int n_in,
                              void* d_out, int out_size)
{
    const float* a = (const float*)d_in[0];
    const float* b = (const float*)d_in[1];
    // d_in[2..5] = weight_ih, weight_hh, bias_ih, bias_hh — hardcoded
    // (1,1,0,0) in the reference; semantics folded into the adder.
    float* out = (float*)d_out;

    const int total_threads = BATCH * 32;      // one warp per row
    const int block = 256;
    const int grid  = (total_threads + block - 1) / block;
    adder_kernel<<<grid, block>>>(a, b, out);
}

// round 3
// speedup vs baseline: 1.2709x; 1.2709x over previous
#include <cuda_runtime.h>
#include <cstdint>

// Base-10 addition of digit arrays (B=524288 rows x 64 digits), exact fp32.
//
// Geometry: 16 lanes per row, each lane owns a contiguous 4-digit segment
// (one float4), 2 rows per warp. Every LDG.128/STG.128 is a fully
// contiguous 512B warp access.
//
// Carry resolution: each lane ripples its 4 digits twice (carry-in 0 and 1),
// yielding segment carry-outs G (=chain0) and G|P (=chain1). Two ballots
// collect these bits; the per-row 16-bit carry-lookahead is solved with the
// adder identity:
//     decimal carries == binary carries of (G|P) + G
//     carry-in mask M  = P ^ ((G|P) + G)        (P = GP & ~G)
// Each lane then selects its precomputed digit set. No shuffles.

static constexpr int BATCH   = 524288;
static constexpr int SEQ_LEN = 64;

__global__ __launch_bounds__(256)
void adder_kernel(const float4* __restrict__ a4,
                  const float4* __restrict__ b4,
                  float4* __restrict__ o4)
{
    const unsigned tid  = blockIdx.x * blockDim.x + threadIdx.x;
    const unsigned lane = tid & 31u;
    const unsigned warp = tid >> 5;
    const unsigned sub  = lane & 15u;   // segment index within row (sub=0 -> LSB segment)
    const unsigned rsel = lane >> 4;    // which of the warp's 2 rows
    const unsigned row  = warp * 2u + rsel;
    if (row >= (unsigned)BATCH) return;

    // Segment sub owns LSB-first positions [4*sub, 4*sub+3], i.e. columns
    // [60-4*sub, 63-4*sub] -> float4 column index f = 15 - sub.
    // Within the float4: .w = segment digit 0 (least significant), .x = digit 3.
    const unsigned f   = 15u - sub;
    const size_t   idx = (size_t)row * (SEQ_LEN / 4) + f;

    const float4 av = a4[idx];
    const float4 bv = b4[idx];

    const float s0 = av.w + bv.w;   // all values integers 0..9 -> sums exact
    const float s1 = av.z + bv.z;
    const float s2 = av.y + bv.y;
    const float s3 = av.x + bv.x;

    // Chain 0: segment ripple with carry-in = 0.
    float t, k0;
    float d00, d01, d02, d03;
    t = s0;        k0 = (t >= 10.f) ? 1.f : 0.f;  d00 = fmaf(-10.f, k0, t);
    t = s1 + k0;   k0 = (t >= 10.f) ? 1.f : 0.f;  d01 = fmaf(-10.f, k0, t);
    t = s2 + k0;   k0 = (t >= 10.f) ? 1.f : 0.f;  d02 = fmaf(-10.f, k0, t);
    t = s3 + k0;   k0 = (t >= 10.f) ? 1.f : 0.f;  d03 = fmaf(-10.f, k0, t);

    // Chain 1: segment ripple with carry-in = 1.
    float k1;
    float d10, d11, d12, d13;
    t = s0 + 1.f;  k1 = (t >= 10.f) ? 1.f : 0.f;  d10 = fmaf(-10.f, k1, t);
    t = s1 + k1;   k1 = (t >= 10.f) ? 1.f : 0.f;  d11 = fmaf(-10.f, k1, t);
    t = s2 + k1;   k1 = (t >= 10.f) ? 1.f : 0.f;  d12 = fmaf(-10.f, k1, t);
    t = s3 + k1;   k1 = (t >= 10.f) ? 1.f : 0.f;  d13 = fmaf(-10.f, k1, t);

    // Segment generate (k0) and generate-or-propagate (k1) bits, warp-wide.
    const unsigned gmask  = __ballot_sync(0xFFFFFFFFu, k0 != 0.f);
    const unsigned gpmask = __ballot_sync(0xFFFFFFFFu, k1 != 0.f);

    // Per-row 16-bit carry lookahead (rows must not leak carries into each other).
    const unsigned sh  = rsel << 4;
    const unsigned gm  = (gmask  >> sh) & 0xFFFFu;
    const unsigned gpm = (gpmask >> sh) & 0xFFFFu;
    const unsigned pm  = gpm & ~gm;
    const unsigned M   = pm ^ (gpm + gm);        // bit s = carry-in to segment s
    const bool cin = (M >> sub) & 1u;

    float4 ov;
    ov.w = cin ? d10 : d00;
    ov.z = cin ? d11 : d01;
    ov.y = cin ? d12 : d02;
    ov.x = cin ? d13 : d03;
    o4[idx] = ov;
}

extern "C" void kernel_launch(void* const* d_in, const int* in_sizes, int n_in,
                              void* d_out, int out_size)
{
    const float4* a = (const float4*)d_in[0];
    const float4* b = (const float4*)d_in[1];
    // d_in[2..5] = weight_ih, weight_hh, bias_ih, bias_hh — hardcoded
    // (1,1,0,0) in the reference; semantics folded into the adder.
    float4* out = (float4*)d_out;

    const int total_threads = (BATCH / 2) * 32;   // 2 rows per warp
    const int block = 256;
    const int grid  = (total_threads + block - 1) / block;
    adder_kernel<<<grid, block>>>(a, b, out);
}